// round 3
// baseline (speedup 1.0000x reference)
#include <cuda_runtime.h>
#include <math.h>

#define BLOCK 128
#define GRID 1024

__device__ float g_Ej[16000000];
__device__ float g_Em[8000000];
__device__ float g_pA[GRID*17], g_pB[GRID*17], g_pD[GRID*17], g_pE[GRID*17];
__device__ float g_pV[2][GRID]; __device__ int g_pI[2][GRID]; __device__ float g_pS[2][GRID];
__device__ float g_g1[16], g_g2[16], g_ejs[16];
__device__ float g_logpj; __device__ int g_selj; __device__ int g_mk;

__device__ __forceinline__ float2 ffma2(float2 a, float2 b, float2 c) {
    unsigned long long ua, ub, uc, ur; float2 r;
    asm("mov.b64 %0,{%1,%2};" : "=l"(ua) : "f"(a.x), "f"(a.y));
    asm("mov.b64 %0,{%1,%2};" : "=l"(ub) : "f"(b.x), "f"(b.y));
    asm("mov.b64 %0,{%1,%2};" : "=l"(uc) : "f"(c.x), "f"(c.y));
    asm("fma.rn.f32x2 %0,%1,%2,%3;" : "=l"(ur) : "l"(ua), "l"(ub), "l"(uc));
    asm("mov.b64 {%0,%1},%2;" : "=f"(r.x), "=f"(r.y) : "l"(ur));
    return r;
}
__device__ __forceinline__ float ftanh(float x) {
    float e = __expf(2.0f * x);
    return __fdividef(e - 1.0f, e + 1.0f);
}
// 4-row 16x16 matvec: out[r][j] = b[j] + sum_d x[r][d]*W[j][d]
__device__ __forceinline__ void mv4(const float2* __restrict__ W2, const float* __restrict__ bsh,
                                    const float2 (&x)[4][8], float2 (&o)[4][8]) {
#pragma unroll
    for (int j = 0; j < 16; j++) {
        float2 a0 = {0,0}, a1 = {0,0}, a2 = {0,0}, a3 = {0,0};
#pragma unroll
        for (int d = 0; d < 8; d++) {
            float2 w = W2[j*8+d];
            a0 = ffma2(x[0][d], w, a0); a1 = ffma2(x[1][d], w, a1);
            a2 = ffma2(x[2][d], w, a2); a3 = ffma2(x[3][d], w, a3);
        }
        float b = bsh[j];
        float v0 = a0.x+a0.y+b, v1 = a1.x+a1.y+b, v2 = a2.x+a2.y+b, v3 = a3.x+a3.y+b;
        if (j&1) { o[0][j>>1].y=v0; o[1][j>>1].y=v1; o[2][j>>1].y=v2; o[3][j>>1].y=v3; }
        else     { o[0][j>>1].x=v0; o[1][j>>1].x=v1; o[2][j>>1].x=v2; o[3][j>>1].x=v3; }
    }
}
__device__ __forceinline__ void tanh4(float2 (&v)[4][8]) {
#pragma unroll
    for (int r = 0; r < 4; r++)
#pragma unroll
        for (int k = 0; k < 8; k++) { v[r][k].x = ftanh(v[r][k].x); v[r][k].y = ftanh(v[r][k].y); }
}
__device__ __forceinline__ float dotVtanh(const float2 (&row)[8], const float* __restrict__ sV) {
    float l = 0.f;
#pragma unroll
    for (int k = 0; k < 8; k++) { l += sV[2*k]*ftanh(row[k].x); l += sV[2*k+1]*ftanh(row[k].y); }
    return l;
}
__device__ __forceinline__ void loadr(const float* __restrict__ X, int row, float2 (&x)[8], bool ok) {
    if (ok) {
        const float4* p = (const float4*)(X + row*16);
#pragma unroll
        for (int q = 0; q < 4; q++) { float4 u = p[q]; x[2*q] = make_float2(u.x,u.y); x[2*q+1] = make_float2(u.z,u.w); }
    } else {
#pragma unroll
        for (int k = 0; k < 8; k++) x[k] = make_float2(0.f,0.f);
    }
}
__device__ __forceinline__ void redu17(float (&acc)[17], float* __restrict__ dst) {
#pragma unroll
    for (int k = 0; k < 17; k++)
#pragma unroll
        for (int o = 16; o > 0; o >>= 1) acc[k] += __shfl_down_sync(0xffffffffu, acc[k], o);
    __shared__ float red[4][17];
    int lane = threadIdx.x & 31, wid = threadIdx.x >> 5;
    if (lane == 0) {
#pragma unroll
        for (int k = 0; k < 17; k++) red[wid][k] = acc[k];
    }
    __syncthreads();
    if (threadIdx.x < 17) {
        float s = 0.f;
#pragma unroll
        for (int w = 0; w < 4; w++) s += red[w][threadIdx.x];
        dst[threadIdx.x] = s;
    }
}
__device__ __forceinline__ void loadq(const float* __restrict__ Wq, const float* __restrict__ bq,
                                      const float* __restrict__ qs, float* sQ) {
    int t = threadIdx.x;
    if (t < 16) {
        float q = bq[t];
#pragma unroll
        for (int d = 0; d < 16; d++) q += qs[d] * Wq[t*16+d];
        sQ[t] = q;
    }
}

// ---- mask dtype detect: 0 = 4-byte (int32/float32), 1 = byte-packed bool ----
__global__ void k_detect(const unsigned* __restrict__ m, int n) {
    __shared__ int fl;
    if (threadIdx.x == 0) fl = 0;
    __syncthreads();
    int words = n >> 2; if (words > 4096) words = 4096;
    int f = 0;
    for (int i = threadIdx.x; i < words; i += blockDim.x) {
        unsigned w = m[i];
        if (w != 0u && w != 1u && w != 0x3F800000u) f = 1;
    }
    if (f) atomicOr(&fl, 1);
    __syncthreads();
    if (threadIdx.x == 0) g_mk = fl;
}

// ---- pass: embed + glimpse-1 accumulate ----
__global__ void __launch_bounds__(BLOCK) k_emb(
    const float* __restrict__ X, int N, int which,
    const float* __restrict__ W1, const float* __restrict__ b1,
    const float* __restrict__ W2g, const float* __restrict__ b2,
    const float* __restrict__ Wr, const float* __restrict__ V,
    const float* __restrict__ Wq, const float* __restrict__ bq,
    const float* __restrict__ qs)
{
    __shared__ float2 sW1[128], sW2[128], sWr[128];
    __shared__ float sb1[16], sb2[16], sV[16], sQ[16];
    int tid = threadIdx.x;
    for (int i = tid; i < 256; i += BLOCK) {
        ((float*)sW1)[i] = W1[i]; ((float*)sW2)[i] = W2g[i]; ((float*)sWr)[i] = Wr[i];
    }
    if (tid < 16) { sb1[tid] = b1[tid]; sb2[tid] = b2[tid]; sV[tid] = V[tid]; }
    loadq(Wq, bq, qs, sQ);
    __syncthreads();

    float* Eout = which ? g_Em : g_Ej;
    float* part = which ? g_pB : g_pA;
    float S = 0.f; float2 Wa[8];
#pragma unroll
    for (int k = 0; k < 8; k++) Wa[k] = make_float2(0.f,0.f);

    for (int base = blockIdx.x * BLOCK * 4; base < N; base += GRID * BLOCK * 4) {
        float2 A[4][8], B[4][8]; bool ok[4]; int rows[4];
#pragma unroll
        for (int r = 0; r < 4; r++) { rows[r] = base + tid + r*BLOCK; ok[r] = rows[r] < N; loadr(X, rows[r], A[r], ok[r]); }
        mv4(sW1, sb1, A, B); tanh4(B);
        mv4(sW2, sb2, B, A); tanh4(A);          // A = embeddings
        float4* E4 = (float4*)Eout;
#pragma unroll
        for (int r = 0; r < 4; r++) if (ok[r])
#pragma unroll
            for (int q = 0; q < 4; q++)
                E4[rows[r]*4+q] = make_float4(A[r][2*q].x, A[r][2*q].y, A[r][2*q+1].x, A[r][2*q+1].y);
        mv4(sWr, sQ, A, B);                     // B = q' + E@Wr^T
#pragma unroll
        for (int r = 0; r < 4; r++) if (ok[r]) {
            float w = __expf(dotVtanh(B[r], sV));
            S += w; float2 wp = make_float2(w,w);
#pragma unroll
            for (int k = 0; k < 8; k++) Wa[k] = ffma2(wp, A[r][k], Wa[k]);
        }
    }
    float acc[17]; acc[0] = S;
#pragma unroll
    for (int k = 0; k < 8; k++) { acc[1+2*k] = Wa[k].x; acc[2+2*k] = Wa[k].y; }
    redu17(acc, part + blockIdx.x*17);
}

// ---- pass: glimpse-2 accumulate over stored E ----
__global__ void __launch_bounds__(BLOCK) k_gl(
    int which, int N,
    const float* __restrict__ Wr, const float* __restrict__ V,
    const float* __restrict__ Wq, const float* __restrict__ bq)
{
    __shared__ float2 sWr[128];
    __shared__ float sV[16], sQ[16];
    int tid = threadIdx.x;
    for (int i = tid; i < 256; i += BLOCK) ((float*)sWr)[i] = Wr[i];
    if (tid < 16) sV[tid] = V[tid];
    loadq(Wq, bq, g_ejs, sQ);
    __syncthreads();

    const float* X = which ? g_Em : g_Ej;
    float* part = which ? g_pE : g_pD;
    float S = 0.f; float2 Wa[8];
#pragma unroll
    for (int k = 0; k < 8; k++) Wa[k] = make_float2(0.f,0.f);

    for (int base = blockIdx.x * BLOCK * 4; base < N; base += GRID * BLOCK * 4) {
        float2 A[4][8], B[4][8]; bool ok[4];
#pragma unroll
        for (int r = 0; r < 4; r++) { int row = base + tid + r*BLOCK; ok[r] = row < N; loadr(X, row, A[r], ok[r]); }
        mv4(sWr, sQ, A, B);
#pragma unroll
        for (int r = 0; r < 4; r++) if (ok[r]) {
            float w = __expf(dotVtanh(B[r], sV));
            S += w; float2 wp = make_float2(w,w);
#pragma unroll
            for (int k = 0; k < 8; k++) Wa[k] = ffma2(wp, A[r][k], Wa[k]);
        }
    }
    float acc[17]; acc[0] = S;
#pragma unroll
    for (int k = 0; k < 8; k++) { acc[1+2*k] = Wa[k].x; acc[2+2*k] = Wa[k].y; }
    redu17(acc, part + blockIdx.x*17);
}

// ---- pass: pointer logits -> per-block argmax + sumexp ----
__global__ void __launch_bounds__(BLOCK) k_arg(
    int which, int N,
    const float* __restrict__ Wr, const float* __restrict__ V,
    const float* __restrict__ Wq, const float* __restrict__ bq,
    const void* __restrict__ maskp)
{
    __shared__ float2 sWr[128];
    __shared__ float sV[16], sQ[16];
    int tid = threadIdx.x;
    for (int i = tid; i < 256; i += BLOCK) ((float*)sWr)[i] = Wr[i];
    if (tid < 16) sV[tid] = V[tid];
    loadq(Wq, bq, which ? g_g2 : g_g1, sQ);
    __syncthreads();

    const float* X = which ? g_Em : g_Ej;
    int mk = g_mk;
    float best = -3e38f, sum = 0.f; int bi = 0x7fffffff;

    for (int base = blockIdx.x * BLOCK * 4; base < N; base += GRID * BLOCK * 4) {
        float2 A[4][8], B[4][8]; bool ok[4]; int rows[4];
#pragma unroll
        for (int r = 0; r < 4; r++) { rows[r] = base + tid + r*BLOCK; ok[r] = rows[r] < N; loadr(X, rows[r], A[r], ok[r]); }
        mv4(sWr, sQ, A, B);
#pragma unroll
        for (int r = 0; r < 4; r++) if (ok[r]) {
            bool pass = true;
            if (maskp) {
                if (mk) pass = ((const unsigned char*)maskp)[rows[r]] != 0;
                else    pass = ((const unsigned*)maskp)[rows[r]] != 0u;
            }
            if (pass) {
                float l = dotVtanh(B[r], sV);
                sum += __expf(l);
                if (l > best) { best = l; bi = rows[r]; }
            }
        }
    }
#pragma unroll
    for (int o = 16; o > 0; o >>= 1) {
        float ov = __shfl_down_sync(0xffffffffu, best, o);
        int   oi = __shfl_down_sync(0xffffffffu, bi, o);
        sum += __shfl_down_sync(0xffffffffu, sum, o);
        if (ov > best || (ov == best && oi < bi)) { best = ov; bi = oi; }
    }
    __shared__ float wv[4], ws[4]; __shared__ int wi[4];
    int lane = tid & 31, wid = tid >> 5;
    if (lane == 0) { wv[wid] = best; wi[wid] = bi; ws[wid] = sum; }
    __syncthreads();
    if (tid == 0) {
        float bv = wv[0]; int ix = wi[0]; float s = ws[0];
#pragma unroll
        for (int w = 1; w < 4; w++) {
            if (wv[w] > bv || (wv[w] == bv && wi[w] < ix)) { bv = wv[w]; ix = wi[w]; }
            s += ws[w];
        }
        g_pV[which][blockIdx.x] = bv; g_pI[which][blockIdx.x] = ix; g_pS[which][blockIdx.x] = s;
    }
}

// ---- finalize glimpse: g = tanh(cat(q0, gA, gB) @ W^T + b) ----
__global__ void k_fing(int which, const float* __restrict__ lastj,
                       const float* __restrict__ W, const float* __restrict__ b)
{
    __shared__ float sA[17], sB[17], cat[48];
    const float* pA = which ? g_pD : g_pA;
    const float* pB = which ? g_pE : g_pB;
    int t = threadIdx.x;                     // 128 threads
    int col = t % 17, grp = t / 17;          // 7 groups (last few threads idle)
    __shared__ float tmpA[7][17], tmpB[7][17];
    if (grp < 7) {
        float a = 0.f, c = 0.f;
        for (int i = grp; i < GRID; i += 7) { a += pA[i*17+col]; c += pB[i*17+col]; }
        tmpA[grp][col] = a; tmpB[grp][col] = c;
    }
    __syncthreads();
    if (t < 17) {
        float a = 0.f, c = 0.f;
#pragma unroll
        for (int g = 0; g < 7; g++) { a += tmpA[g][t]; c += tmpB[g][t]; }
        sA[t] = a; sB[t] = c;
    }
    __syncthreads();
    if (t < 16) {
        cat[t]      = which ? g_ejs[t] : lastj[t];
        cat[16 + t] = sA[1+t] / sA[0];
        cat[32 + t] = sB[1+t] / sB[0];
    }
    __syncthreads();
    if (t < 16) {
        float g = b[t];
#pragma unroll
        for (int d = 0; d < 48; d++) g += cat[d] * W[t*48+d];
        float* dst = which ? g_g2 : g_g1;
        dst[t] = tanhf(g);
    }
}

// ---- finalize job argmax: sel_j, logp_j, e_js ----
__global__ void k_finj() {
    int t = threadIdx.x;                     // 128 threads
    float bv = -3e38f, s = 0.f; int bi = 0x7fffffff;
    for (int i = t; i < GRID; i += 128) {
        float v = g_pV[0][i]; int ix = g_pI[0][i];
        if (v > bv || (v == bv && ix < bi)) { bv = v; bi = ix; }
        s += g_pS[0][i];
    }
#pragma unroll
    for (int o = 16; o > 0; o >>= 1) {
        float ov = __shfl_down_sync(0xffffffffu, bv, o);
        int   oi = __shfl_down_sync(0xffffffffu, bi, o);
        s += __shfl_down_sync(0xffffffffu, s, o);
        if (ov > bv || (ov == bv && oi < bi)) { bv = ov; bi = oi; }
    }
    __shared__ float wv[4], ws[4]; __shared__ int wi[4]; __shared__ int ssel;
    int lane = t & 31, wid = t >> 5;
    if (lane == 0) { wv[wid] = bv; wi[wid] = bi; ws[wid] = s; }
    __syncthreads();
    if (t == 0) {
        float v = wv[0]; int ix = wi[0]; float ss = ws[0];
#pragma unroll
        for (int w = 1; w < 4; w++) {
            if (wv[w] > v || (wv[w] == v && wi[w] < ix)) { v = wv[w]; ix = wi[w]; }
            ss += ws[w];
        }
        if (ix == 0x7fffffff) ix = 0;
        g_selj = ix; g_logpj = v - logf(ss); ssel = ix;
    }
    __syncthreads();
    if (t < 16) g_ejs[t] = g_Ej[ssel*16 + t];
}

// ---- finalize machine argmax + write output ----
__global__ void k_finm(float* __restrict__ out) {
    int t = threadIdx.x;
    float bv = -3e38f, s = 0.f; int bi = 0x7fffffff;
    for (int i = t; i < GRID; i += 128) {
        float v = g_pV[1][i]; int ix = g_pI[1][i];
        if (v > bv || (v == bv && ix < bi)) { bv = v; bi = ix; }
        s += g_pS[1][i];
    }
#pragma unroll
    for (int o = 16; o > 0; o >>= 1) {
        float ov = __shfl_down_sync(0xffffffffu, bv, o);
        int   oi = __shfl_down_sync(0xffffffffu, bi, o);
        s += __shfl_down_sync(0xffffffffu, s, o);
        if (ov > bv || (ov == bv && oi < bi)) { bv = ov; bi = oi; }
    }
    __shared__ float wv[4], ws[4]; __shared__ int wi[4];
    int lane = t & 31, wid = t >> 5;
    if (lane == 0) { wv[wid] = bv; wi[wid] = bi; ws[wid] = s; }
    __syncthreads();
    if (t == 0) {
        float v = wv[0]; int ix = wi[0]; float ss = ws[0];
#pragma unroll
        for (int w = 1; w < 4; w++) {
            if (wv[w] > v || (wv[w] == v && wi[w] < ix)) { v = wv[w]; ix = wi[w]; }
            ss += ws[w];
        }
        if (ix == 0x7fffffff) ix = 0;
        out[0] = (float)g_selj;
        out[1] = (float)ix;
        out[2] = g_logpj + (v - logf(ss));
    }
}

extern "C" void kernel_launch(void* const* d_in, const int* in_sizes, int n_in,
                              void* d_out, int out_size) {
    const float* jobs  = (const float*)d_in[0];
    const float* machs = (const float*)d_in[1];
    const void*  mask  = d_in[2];
    const float *jW1=(const float*)d_in[3], *jb1=(const float*)d_in[4], *jW2=(const float*)d_in[5], *jb2=(const float*)d_in[6];
    const float *mW1=(const float*)d_in[7], *mb1=(const float*)d_in[8], *mW2=(const float*)d_in[9], *mb2=(const float*)d_in[10];
    const float *ajWq=(const float*)d_in[11], *ajbq=(const float*)d_in[12], *ajWr=(const float*)d_in[13], *ajV=(const float*)d_in[14];
    const float *amWq=(const float*)d_in[15], *ambq=(const float*)d_in[16], *amWr=(const float*)d_in[17], *amV=(const float*)d_in[18];
    const float *jaWq=(const float*)d_in[19], *jabq=(const float*)d_in[20], *jaWr=(const float*)d_in[21], *jaV=(const float*)d_in[22];
    const float *maWq=(const float*)d_in[23], *mabq=(const float*)d_in[24], *maWr=(const float*)d_in[25], *maV=(const float*)d_in[26];
    const float *g1W=(const float*)d_in[27], *g1b=(const float*)d_in[28];
    const float *g2W=(const float*)d_in[29], *g2b=(const float*)d_in[30];
    const float *lastj=(const float*)d_in[31];
    int Nj = in_sizes[0] / 16;
    int Nm = in_sizes[1] / 16;
    float* out = (float*)d_out;

    k_detect<<<1, 256>>>((const unsigned*)mask, in_sizes[2]);
    // embeddings + glimpse-1 partials (query = last_j)
    k_emb<<<GRID, BLOCK>>>(jobs,  Nj, 0, jW1, jb1, jW2, jb2, ajWr, ajV, ajWq, ajbq, lastj);
    k_emb<<<GRID, BLOCK>>>(machs, Nm, 1, mW1, mb1, mW2, mb2, amWr, amV, amWq, ambq, lastj);
    k_fing<<<1, 128>>>(0, lastj, g1W, g1b);           // -> g_g1
    // job pointer: logits over E_j, masked, query g1
    k_arg<<<GRID, BLOCK>>>(0, Nj, jaWr, jaV, jaWq, jabq, mask);
    k_finj<<<1, 128>>>();                             // -> g_selj, g_logpj, g_ejs
    // glimpse-2 partials (query = e_js)
    k_gl<<<GRID, BLOCK>>>(0, Nj, ajWr, ajV, ajWq, ajbq);
    k_gl<<<GRID, BLOCK>>>(1, Nm, amWr, amV, amWq, ambq);
    k_fing<<<1, 128>>>(1, lastj, g2W, g2b);           // -> g_g2
    // machine pointer: logits over E_m, query g2
    k_arg<<<GRID, BLOCK>>>(1, Nm, maWr, maV, maWq, mabq, nullptr);
    k_finm<<<1, 128>>>(out);
    (void)n_in; (void)out_size;
}

// round 4
// speedup vs baseline: 1.2368x; 1.2368x over previous
#include <cuda_runtime.h>
#include <math.h>

#define BLOCK 128
#define NB 296
#define BJ 200
#define NBM (NB - BJ)
typedef unsigned long long u64;

__device__ float g_Ej[16000000];
__device__ float g_Em[8000000];
__device__ float g_pJ[BJ * 17], g_pM[NBM * 17];
__device__ float g_aV[NB]; __device__ int g_aI[NB]; __device__ float g_aS[NB];
__device__ float g_g1[16], g_g2[16], g_ejs[16];
__device__ float g_logpj; __device__ int g_selj;
__device__ int g_c0, g_c1, g_c2, g_c3;

__device__ __forceinline__ u64 F2(u64 a, u64 b, u64 c) {
    u64 r; asm("fma.rn.f32x2 %0,%1,%2,%3;" : "=l"(r) : "l"(a), "l"(b), "l"(c)); return r;
}
__device__ __forceinline__ u64 pack2(float lo, float hi) {
    u64 r; asm("mov.b64 %0,{%1,%2};" : "=l"(r) : "f"(lo), "f"(hi)); return r;
}
__device__ __forceinline__ float2 unpack2(u64 v) {
    float2 r; asm("mov.b64 {%0,%1},%2;" : "=f"(r.x), "=f"(r.y) : "l"(v)); return r;
}
__device__ __forceinline__ float ftanh(float x) {
    float e = __expf(2.0f * x);
    return __fdividef(e - 1.0f, e + 1.0f);
}

// 4-row 16x16 matvec on packed pairs: o[r][j] = b[j] + sum_d x[r][d]*W[j][d]
__device__ __forceinline__ void mv4(const u64* __restrict__ sW, const float* __restrict__ sb,
                                    const u64 (&x)[4][8], float (&o)[4][16]) {
#pragma unroll
    for (int j = 0; j < 16; j++) {
        u64 a0 = 0ull, a1 = 0ull, a2 = 0ull, a3 = 0ull;
#pragma unroll
        for (int d = 0; d < 8; d++) {
            u64 w = sW[j * 8 + d];
            a0 = F2(x[0][d], w, a0); a1 = F2(x[1][d], w, a1);
            a2 = F2(x[2][d], w, a2); a3 = F2(x[3][d], w, a3);
        }
        float b = sb[j]; float2 t;
        t = unpack2(a0); o[0][j] = t.x + t.y + b;
        t = unpack2(a1); o[1][j] = t.x + t.y + b;
        t = unpack2(a2); o[2][j] = t.x + t.y + b;
        t = unpack2(a3); o[3][j] = t.x + t.y + b;
    }
}
// tanh + repack rows
__device__ __forceinline__ void tp4(const float (&o)[4][16], u64 (&x)[4][8]) {
#pragma unroll
    for (int r = 0; r < 4; r++)
#pragma unroll
        for (int k = 0; k < 8; k++)
            x[r][k] = pack2(ftanh(o[r][2 * k]), ftanh(o[r][2 * k + 1]));
}
__device__ __forceinline__ void loadrow(const float* __restrict__ X, int row, u64 (&x)[8], bool ok) {
    if (ok) {
        const ulonglong2* p = (const ulonglong2*)(X + row * 16);
#pragma unroll
        for (int q = 0; q < 4; q++) { ulonglong2 u = p[q]; x[2 * q] = u.x; x[2 * q + 1] = u.y; }
    } else {
#pragma unroll
        for (int k = 0; k < 8; k++) x[k] = 0ull;
    }
}
__device__ __forceinline__ void redu17(float (&acc)[17], float* __restrict__ dst) {
#pragma unroll
    for (int k = 0; k < 17; k++)
#pragma unroll
        for (int o = 16; o > 0; o >>= 1) acc[k] += __shfl_down_sync(0xffffffffu, acc[k], o);
    __shared__ float red[4][17];
    int lane = threadIdx.x & 31, wid = threadIdx.x >> 5;
    if (lane == 0) {
#pragma unroll
        for (int k = 0; k < 17; k++) red[wid][k] = acc[k];
    }
    __syncthreads();
    if (threadIdx.x < 17) {
        float s = 0.f;
#pragma unroll
        for (int w = 0; w < 4; w++) s += red[w][threadIdx.x];
        dst[threadIdx.x] = s;
    }
}

// glimpse finalize (runs in last block of a big pass): g = tanh(cat(q0,gJ,gM) @ W^T + b)
__device__ void fin_g(int t, const float* __restrict__ q0, const float* __restrict__ gW,
                      const float* __restrict__ gb, float* __restrict__ dst, int* cnt) {
    __shared__ float tA[7][17], tB[7][17], sA[17], sB[17], cat[48], sGW[768];
    int col = t % 17, grp = t / 17;
    if (grp < 7) {
        float a = 0.f, b = 0.f;
        for (int i = grp; i < BJ;  i += 7) a += g_pJ[i * 17 + col];
        for (int i = grp; i < NBM; i += 7) b += g_pM[i * 17 + col];
        tA[grp][col] = a; tB[grp][col] = b;
    }
    for (int i = t; i < 768; i += BLOCK) sGW[i] = gW[i];
    __syncthreads();
    if (t < 17) {
        float a = 0.f, b = 0.f;
#pragma unroll
        for (int g = 0; g < 7; g++) { a += tA[g][t]; b += tB[g][t]; }
        sA[t] = a; sB[t] = b;
    }
    __syncthreads();
    if (t < 16) {
        cat[t] = q0[t];
        cat[16 + t] = sA[1 + t] / sA[0];
        cat[32 + t] = sB[1 + t] / sB[0];
    }
    __syncthreads();
    if (t < 16) {
        float g = gb[t];
#pragma unroll
        for (int d = 0; d < 48; d++) g += cat[d] * sGW[t * 48 + d];
        dst[t] = tanhf(g);
    }
    if (t == 0) *cnt = 0;
}

// argmax finalize: which==0 -> sel_j/logpj/e_js ; which==1 -> write output
__device__ void fin_arg(int t, int which, float* __restrict__ out, int* cnt) {
    float bv = -3e38f, s = 0.f; int bi = 0x7fffffff;
    for (int i = t; i < NB; i += BLOCK) {
        float v = g_aV[i]; int ix = g_aI[i];
        if (v > bv || (v == bv && ix < bi)) { bv = v; bi = ix; }
        s += g_aS[i];
    }
#pragma unroll
    for (int o = 16; o > 0; o >>= 1) {
        float ov = __shfl_down_sync(0xffffffffu, bv, o);
        int   oi = __shfl_down_sync(0xffffffffu, bi, o);
        s += __shfl_down_sync(0xffffffffu, s, o);
        if (ov > bv || (ov == bv && oi < bi)) { bv = ov; bi = oi; }
    }
    __shared__ float wv[4], ws[4]; __shared__ int wi[4]; __shared__ int ssel;
    int lane = t & 31, wid = t >> 5;
    if (lane == 0) { wv[wid] = bv; wi[wid] = bi; ws[wid] = s; }
    __syncthreads();
    if (t == 0) {
        float v = wv[0]; int ix = wi[0]; float ss = ws[0];
#pragma unroll
        for (int w = 1; w < 4; w++) {
            if (wv[w] > v || (wv[w] == v && wi[w] < ix)) { v = wv[w]; ix = wi[w]; }
            ss += ws[w];
        }
        if (ix == 0x7fffffff) ix = 0;
        if (which == 0) { g_selj = ix; g_logpj = v - logf(ss); ssel = ix; }
        else { out[0] = (float)g_selj; out[1] = (float)ix; out[2] = g_logpj + (v - logf(ss)); }
        *cnt = 0;
    }
    __syncthreads();
    if (which == 0 && t < 16) g_ejs[t] = g_Ej[ssel * 16 + t];
}

// ---- pass 1: embed jobs+machines, glimpse-1 partials, fused g1 finalize ----
__global__ void __launch_bounds__(BLOCK) k_emb(
    const float* __restrict__ jobs, const float* __restrict__ machs, int Nj, int Nm,
    const float* __restrict__ jW1, const float* __restrict__ jb1,
    const float* __restrict__ jW2, const float* __restrict__ jb2,
    const float* __restrict__ mW1, const float* __restrict__ mb1,
    const float* __restrict__ mW2, const float* __restrict__ mb2,
    const float* __restrict__ ajWr, const float* __restrict__ ajV,
    const float* __restrict__ ajWq, const float* __restrict__ ajbq,
    const float* __restrict__ amWr, const float* __restrict__ amV,
    const float* __restrict__ amWq, const float* __restrict__ ambq,
    const float* __restrict__ lastj, const float* __restrict__ g1W, const float* __restrict__ g1b)
{
    int t = threadIdx.x;
    int side = blockIdx.x >= BJ;
    int lb = side ? blockIdx.x - BJ : blockIdx.x;
    int nb = side ? NBM : BJ;
    const float* X = side ? machs : jobs;
    int N = side ? Nm : Nj;
    float* Eo = side ? g_Em : g_Ej;
    float* part = (side ? g_pM : g_pJ) + lb * 17;
    const float* W1 = side ? mW1 : jW1; const float* b1 = side ? mb1 : jb1;
    const float* W2 = side ? mW2 : jW2; const float* b2 = side ? mb2 : jb2;
    const float* Wr = side ? amWr : ajWr; const float* V = side ? amV : ajV;
    const float* Wq = side ? amWq : ajWq; const float* bq = side ? ambq : ajbq;

    __shared__ u64 sW1[128], sW2[128], sWr[128];
    __shared__ float sb1[16], sb2[16], sV[16], sQ[16];
    for (int i = t; i < 128; i += BLOCK) {
        sW1[i] = ((const u64*)W1)[i]; sW2[i] = ((const u64*)W2)[i]; sWr[i] = ((const u64*)Wr)[i];
    }
    if (t < 16) {
        sb1[t] = b1[t]; sb2[t] = b2[t]; sV[t] = V[t];
        float q = bq[t];
#pragma unroll
        for (int d = 0; d < 16; d++) q += lastj[d] * Wq[t * 16 + d];
        sQ[t] = q;
    }
    __syncthreads();

    float S = 0.f; u64 Wa[8];
#pragma unroll
    for (int k = 0; k < 8; k++) Wa[k] = 0ull;

    for (int base = lb * BLOCK * 4; base < N; base += nb * BLOCK * 4) {
        u64 x[4][8]; float o[4][16]; bool ok[4]; int rows[4];
#pragma unroll
        for (int r = 0; r < 4; r++) { rows[r] = base + t + r * BLOCK; ok[r] = rows[r] < N; loadrow(X, rows[r], x[r], ok[r]); }
        mv4(sW1, sb1, x, o); tp4(o, x);
        mv4(sW2, sb2, x, o); tp4(o, x);     // x = packed embeddings
#pragma unroll
        for (int r = 0; r < 4; r++) if (ok[r]) {
            ulonglong2* e = (ulonglong2*)(Eo + rows[r] * 16);
#pragma unroll
            for (int q = 0; q < 4; q++) { ulonglong2 u; u.x = x[r][2 * q]; u.y = x[r][2 * q + 1]; e[q] = u; }
        }
        mv4(sWr, sQ, x, o);                 // o = q' + E@Wr^T
#pragma unroll
        for (int r = 0; r < 4; r++) if (ok[r]) {
            float l = 0.f;
#pragma unroll
            for (int k = 0; k < 16; k++) l += sV[k] * ftanh(o[r][k]);
            float w = __expf(l); S += w;
            u64 wp = pack2(w, w);
#pragma unroll
            for (int k = 0; k < 8; k++) Wa[k] = F2(wp, x[r][k], Wa[k]);
        }
    }
    float acc[17]; acc[0] = S;
#pragma unroll
    for (int k = 0; k < 8; k++) { float2 u = unpack2(Wa[k]); acc[1 + 2 * k] = u.x; acc[2 + 2 * k] = u.y; }
    redu17(acc, part);
    __syncthreads();
    __shared__ int lastb;
    if (t == 0) { __threadfence(); lastb = (atomicAdd(&g_c0, 1) == NB - 1); }
    __syncthreads();
    if (lastb) fin_g(t, lastj, g1W, g1b, g_g1, &g_c0);
}

// ---- pass 3: glimpse-2 over stored embeddings (jobs+machines), fused g2 finalize ----
__global__ void __launch_bounds__(BLOCK) k_gl(
    int Nj, int Nm,
    const float* __restrict__ ajWr, const float* __restrict__ ajV,
    const float* __restrict__ ajWq, const float* __restrict__ ajbq,
    const float* __restrict__ amWr, const float* __restrict__ amV,
    const float* __restrict__ amWq, const float* __restrict__ ambq,
    const float* __restrict__ g2W, const float* __restrict__ g2b)
{
    int t = threadIdx.x;
    int side = blockIdx.x >= BJ;
    int lb = side ? blockIdx.x - BJ : blockIdx.x;
    int nb = side ? NBM : BJ;
    const float* X = side ? g_Em : g_Ej;
    int N = side ? Nm : Nj;
    float* part = (side ? g_pM : g_pJ) + lb * 17;
    const float* Wr = side ? amWr : ajWr; const float* V = side ? amV : ajV;
    const float* Wq = side ? amWq : ajWq; const float* bq = side ? ambq : ajbq;

    __shared__ u64 sWr[128];
    __shared__ float sV[16], sQ[16];
    for (int i = t; i < 128; i += BLOCK) sWr[i] = ((const u64*)Wr)[i];
    if (t < 16) {
        sV[t] = V[t];
        float q = bq[t];
#pragma unroll
        for (int d = 0; d < 16; d++) q += g_ejs[d] * Wq[t * 16 + d];
        sQ[t] = q;
    }
    __syncthreads();

    float S = 0.f; u64 Wa[8];
#pragma unroll
    for (int k = 0; k < 8; k++) Wa[k] = 0ull;

    for (int base = lb * BLOCK * 4; base < N; base += nb * BLOCK * 4) {
        u64 x[4][8]; float o[4][16]; bool ok[4];
#pragma unroll
        for (int r = 0; r < 4; r++) { int row = base + t + r * BLOCK; ok[r] = row < N; loadrow(X, row, x[r], ok[r]); }
        mv4(sWr, sQ, x, o);
#pragma unroll
        for (int r = 0; r < 4; r++) if (ok[r]) {
            float l = 0.f;
#pragma unroll
            for (int k = 0; k < 16; k++) l += sV[k] * ftanh(o[r][k]);
            float w = __expf(l); S += w;
            u64 wp = pack2(w, w);
#pragma unroll
            for (int k = 0; k < 8; k++) Wa[k] = F2(wp, x[r][k], Wa[k]);
        }
    }
    float acc[17]; acc[0] = S;
#pragma unroll
    for (int k = 0; k < 8; k++) { float2 u = unpack2(Wa[k]); acc[1 + 2 * k] = u.x; acc[2 + 2 * k] = u.y; }
    redu17(acc, part);
    __syncthreads();
    __shared__ int lastb;
    if (t == 0) { __threadfence(); lastb = (atomicAdd(&g_c2, 1) == NB - 1); }
    __syncthreads();
    if (lastb) fin_g(t, g_ejs, g2W, g2b, g_g2, &g_c2);
}

// ---- passes 2 & 4: pointer logits -> argmax + sumexp, fused finalize ----
__global__ void __launch_bounds__(BLOCK) k_arg(
    int which, int N,
    const float* __restrict__ Wr, const float* __restrict__ V,
    const float* __restrict__ Wq, const float* __restrict__ bq,
    const void* __restrict__ maskp, int nmask, float* __restrict__ out)
{
    int t = threadIdx.x;
    const float* X = which ? g_Em : g_Ej;
    const float* qs = which ? g_g2 : g_g1;
    int* cnt = which ? &g_c3 : &g_c1;

    __shared__ u64 sWr[128];
    __shared__ float sV[16], sQ[16];
    __shared__ int smk;
    if (t == 0) smk = 0;
    for (int i = t; i < 128; i += BLOCK) sWr[i] = ((const u64*)Wr)[i];
    if (t < 16) {
        sV[t] = V[t];
        float q = bq[t];
#pragma unroll
        for (int d = 0; d < 16; d++) q += qs[d] * Wq[t * 16 + d];
        sQ[t] = q;
    }
    __syncthreads();
    // inline mask dtype detect: 0 = 4-byte elems (int32/float32), 1 = byte bools
    if (maskp) {
        int words = nmask >> 2; if (words > 4096) words = 4096;
        int f = 0;
        for (int i = t; i < words; i += BLOCK) {
            unsigned w = ((const unsigned*)maskp)[i];
            if (w != 0u && w != 1u && w != 0x3F800000u) f = 1;
        }
        if (f) atomicOr(&smk, 1);
    }
    __syncthreads();
    int mk = smk;

    float best = -3e38f, sum = 0.f; int bi = 0x7fffffff;
    for (int base = blockIdx.x * BLOCK * 4; base < N; base += NB * BLOCK * 4) {
        u64 x[4][8]; float o[4][16]; bool ok[4]; int rows[4];
#pragma unroll
        for (int r = 0; r < 4; r++) { rows[r] = base + t + r * BLOCK; ok[r] = rows[r] < N; loadrow(X, rows[r], x[r], ok[r]); }
        mv4(sWr, sQ, x, o);
#pragma unroll
        for (int r = 0; r < 4; r++) if (ok[r]) {
            bool pass = true;
            if (maskp) {
                if (mk) pass = ((const unsigned char*)maskp)[rows[r]] != 0;
                else    pass = ((const unsigned*)maskp)[rows[r]] != 0u;
            }
            if (pass) {
                float l = 0.f;
#pragma unroll
                for (int k = 0; k < 16; k++) l += sV[k] * ftanh(o[r][k]);
                sum += __expf(l);
                if (l > best) { best = l; bi = rows[r]; }
            }
        }
    }
#pragma unroll
    for (int of = 16; of > 0; of >>= 1) {
        float ov = __shfl_down_sync(0xffffffffu, best, of);
        int   oi = __shfl_down_sync(0xffffffffu, bi, of);
        sum += __shfl_down_sync(0xffffffffu, sum, of);
        if (ov > best || (ov == best && oi < bi)) { best = ov; bi = oi; }
    }
    __shared__ float wv[4], ws[4]; __shared__ int wi[4];
    int lane = t & 31, wid = t >> 5;
    if (lane == 0) { wv[wid] = best; wi[wid] = bi; ws[wid] = sum; }
    __syncthreads();
    if (t == 0) {
        float v = wv[0]; int ix = wi[0]; float s = ws[0];
#pragma unroll
        for (int w = 1; w < 4; w++) {
            if (wv[w] > v || (wv[w] == v && wi[w] < ix)) { v = wv[w]; ix = wi[w]; }
            s += ws[w];
        }
        g_aV[blockIdx.x] = v; g_aI[blockIdx.x] = ix; g_aS[blockIdx.x] = s;
    }
    __syncthreads();
    __shared__ int lastb;
    if (t == 0) { __threadfence(); lastb = (atomicAdd(cnt, 1) == NB - 1); }
    __syncthreads();
    if (lastb) fin_arg(t, which, out, cnt);
}

extern "C" void kernel_launch(void* const* d_in, const int* in_sizes, int n_in,
                              void* d_out, int out_size) {
    const float* jobs  = (const float*)d_in[0];
    const float* machs = (const float*)d_in[1];
    const void*  mask  = d_in[2];
    const float *jW1=(const float*)d_in[3], *jb1=(const float*)d_in[4], *jW2=(const float*)d_in[5], *jb2=(const float*)d_in[6];
    const float *mW1=(const float*)d_in[7], *mb1=(const float*)d_in[8], *mW2=(const float*)d_in[9], *mb2=(const float*)d_in[10];
    const float *ajWq=(const float*)d_in[11], *ajbq=(const float*)d_in[12], *ajWr=(const float*)d_in[13], *ajV=(const float*)d_in[14];
    const float *amWq=(const float*)d_in[15], *ambq=(const float*)d_in[16], *amWr=(const float*)d_in[17], *amV=(const float*)d_in[18];
    const float *jaWq=(const float*)d_in[19], *jabq=(const float*)d_in[20], *jaWr=(const float*)d_in[21], *jaV=(const float*)d_in[22];
    const float *maWq=(const float*)d_in[23], *mabq=(const float*)d_in[24], *maWr=(const float*)d_in[25], *maV=(const float*)d_in[26];
    const float *g1W=(const float*)d_in[27], *g1b=(const float*)d_in[28];
    const float *g2W=(const float*)d_in[29], *g2b=(const float*)d_in[30];
    const float *lastj=(const float*)d_in[31];
    int Nj = in_sizes[0] / 16;
    int Nm = in_sizes[1] / 16;
    float* out = (float*)d_out;

    k_emb<<<NB, BLOCK>>>(jobs, machs, Nj, Nm, jW1, jb1, jW2, jb2, mW1, mb1, mW2, mb2,
                         ajWr, ajV, ajWq, ajbq, amWr, amV, amWq, ambq, lastj, g1W, g1b);
    k_arg<<<NB, BLOCK>>>(0, Nj, jaWr, jaV, jaWq, jabq, mask, in_sizes[2], out);
    k_gl <<<NB, BLOCK>>>(Nj, Nm, ajWr, ajV, ajWq, ajbq, amWr, amV, amWq, ambq, g2W, g2b);
    k_arg<<<NB, BLOCK>>>(1, Nm, maWr, maV, maWq, mabq, nullptr, 0, out);
    (void)n_in; (void)out_size;
}